// round 1
// baseline (speedup 1.0000x reference)
#include <cuda_runtime.h>

#define TPB 128
#define SMEM_FLOATS 25088  // w1(512) + w2(4096) + w3(4096) + w4(16384)

// Vectorized global reduction (sm_90+ PTX: red.global.add.v4.f32)
__device__ __forceinline__ void red4(float* p, float a, float b, float c, float d) {
    asm volatile("red.global.add.v4.f32 [%0], {%1, %2, %3, %4};"
                 :: "l"(p), "f"(a), "f"(b), "f"(c), "f"(d) : "memory");
}

__device__ __forceinline__ float silu(float x) {
    return __fdividef(x, 1.0f + __expf(-x));
}

// 64 -> 64 dense layer, weights in shared (row-major [64][64]), uniform LDS.128
__device__ __forceinline__ void dense64(const float* ain, const float* wsh,
                                        float scale, float* aout)
{
    #pragma unroll 1
    for (int jc = 0; jc < 2; jc++) {
        float acc[32];
        #pragma unroll
        for (int jj = 0; jj < 32; jj++) acc[jj] = 0.0f;
        #pragma unroll 4
        for (int i = 0; i < 64; i++) {
            float av = ain[i];
            const float4* wrow = (const float4*)(wsh + i * 64 + jc * 32);
            #pragma unroll
            for (int m = 0; m < 8; m++) {
                float4 w = wrow[m];
                acc[m*4+0] += av * w.x;
                acc[m*4+1] += av * w.y;
                acc[m*4+2] += av * w.z;
                acc[m*4+3] += av * w.w;
            }
        }
        #pragma unroll
        for (int jj = 0; jj < 32; jj++)
            aout[jc * 32 + jj] = silu(acc[jj] * scale);
    }
}

// One irrep (width W): compute mix chunk (32 channels at a time) from h@w4,
// then scale by s (sender feats) and emit W float4 vector-reductions per
// 4-channel group. All indices compile-time after unroll -> pure registers.
template<int W>
__device__ __forceinline__ void irrep_block(
    const float* hh, const float* sw4, int col0,
    const float* __restrict__ sfeat, float* outp, const float (&yv)[W])
{
    #pragma unroll 1
    for (int jc = 0; jc < 2; jc++) {
        float acc[32];
        #pragma unroll
        for (int jj = 0; jj < 32; jj++) acc[jj] = 0.0f;
        #pragma unroll 4
        for (int i = 0; i < 64; i++) {
            float av = hh[i];
            const float4* wrow = (const float4*)(sw4 + i * 256 + col0 + jc * 32);
            #pragma unroll
            for (int m = 0; m < 8; m++) {
                float4 w = wrow[m];
                acc[m*4+0] += av * w.x;
                acc[m*4+1] += av * w.y;
                acc[m*4+2] += av * w.z;
                acc[m*4+3] += av * w.w;
            }
        }
        const int c0 = jc * 32;
        #pragma unroll
        for (int q4 = 0; q4 < 8; q4++) {
            const int c = c0 + q4 * 4;
            float4 s4 = __ldg((const float4*)(sfeat + c));
            // scale = (1/8 from w4 path-norm) * (1/sqrt(AVG_NEIGH)=1/4) = 1/32
            float t[4];
            t[0] = s4.x * acc[q4*4+0] * 0.03125f;
            t[1] = s4.y * acc[q4*4+1] * 0.03125f;
            t[2] = s4.z * acc[q4*4+2] * 0.03125f;
            t[3] = s4.w * acc[q4*4+3] * 0.03125f;
            float vals[4 * W];
            #pragma unroll
            for (int q = 0; q < 4; q++)
                #pragma unroll
                for (int k = 0; k < W; k++)
                    vals[q * W + k] = t[q] * yv[k];
            float* p = outp + c * W;
            #pragma unroll
            for (int m = 0; m < W; m++)
                red4(p + 4 * m, vals[4*m+0], vals[4*m+1], vals[4*m+2], vals[4*m+3]);
        }
    }
}

__global__ void __launch_bounds__(TPB)
mpconv_kernel(const float* __restrict__ vectors,
              const float* __restrict__ node_feats,
              const float* __restrict__ radial,
              const float* __restrict__ w1, const float* __restrict__ w2,
              const float* __restrict__ w3, const float* __restrict__ w4,
              const int* __restrict__ senders, const int* __restrict__ receivers,
              float* __restrict__ out, int n_edges)
{
    extern __shared__ float smem[];
    float* sw1 = smem;           // 512
    float* sw2 = sw1 + 512;      // 4096
    float* sw3 = sw2 + 4096;     // 4096
    float* sw4 = sw3 + 4096;     // 16384

    {   // coalesced float4 weight staging
        float4* d1 = (float4*)sw1; const float4* s1 = (const float4*)w1;
        for (int i = threadIdx.x; i < 128; i += TPB) d1[i] = s1[i];
        float4* d2 = (float4*)sw2; const float4* s2 = (const float4*)w2;
        for (int i = threadIdx.x; i < 1024; i += TPB) d2[i] = s2[i];
        float4* d3 = (float4*)sw3; const float4* s3 = (const float4*)w3;
        for (int i = threadIdx.x; i < 1024; i += TPB) d3[i] = s3[i];
        float4* d4 = (float4*)sw4; const float4* s4 = (const float4*)w4;
        for (int i = threadIdx.x; i < 4096; i += TPB) d4[i] = s4[i];
    }
    __syncthreads();

    int e = blockIdx.x * TPB + threadIdx.x;
    if (e >= n_edges) return;

    // ---- radial MLP ----
    float rr[8];
    {
        const float4* rp = (const float4*)(radial + (size_t)e * 8);
        float4 ra = __ldg(rp), rb = __ldg(rp + 1);
        rr[0]=ra.x; rr[1]=ra.y; rr[2]=ra.z; rr[3]=ra.w;
        rr[4]=rb.x; rr[5]=rb.y; rr[6]=rb.z; rr[7]=rb.w;
    }

    float ha[64], hb[64];
    // layer 1: 8 -> 64, scale 1/sqrt(8)
    #pragma unroll 1
    for (int jc = 0; jc < 2; jc++) {
        float acc[32];
        #pragma unroll
        for (int jj = 0; jj < 32; jj++) acc[jj] = 0.0f;
        #pragma unroll
        for (int i = 0; i < 8; i++) {
            float rv = rr[i];
            const float4* wrow = (const float4*)(sw1 + i * 64 + jc * 32);
            #pragma unroll
            for (int m = 0; m < 8; m++) {
                float4 w = wrow[m];
                acc[m*4+0] += rv * w.x;
                acc[m*4+1] += rv * w.y;
                acc[m*4+2] += rv * w.z;
                acc[m*4+3] += rv * w.w;
            }
        }
        #pragma unroll
        for (int jj = 0; jj < 32; jj++)
            ha[jc * 32 + jj] = silu(acc[jj] * 0.35355339059327373f);
    }
    dense64(ha, sw2, 0.125f, hb);   // layer 2
    dense64(hb, sw3, 0.125f, ha);   // layer 3 -> ha = h3

    // ---- geometry: normalized vector + real spherical harmonics ----
    float vx = __ldg(vectors + 3 * (size_t)e + 0);
    float vy = __ldg(vectors + 3 * (size_t)e + 1);
    float vz = __ldg(vectors + 3 * (size_t)e + 2);
    float inv = 1.0f / (sqrtf(vx*vx + vy*vy + vz*vz) + 1e-12f);
    float x = vx * inv, y = vy * inv, z = vz * inv;

    const float s3  = 1.7320508075688772f;   // sqrt(3)
    const float s5  = 2.23606797749979f;     // sqrt(5)
    const float s15 = 3.872983346207417f;    // sqrt(15)
    const float c33 = 2.091650066335189f;    // sqrt(35/8)
    const float c32 = 10.246950765959598f;   // sqrt(105)
    const float c31 = 1.6201851746019651f;   // sqrt(21/8)
    const float c30 = 1.3228756555322954f;   // 0.5*sqrt(7)

    float z2 = z * z, x2 = x * x, y2 = y * y;
    float yv0[1] = { 1.0f };
    float yv1[3] = { s3 * y, s3 * z, s3 * x };
    float yv2[5] = { s15 * x * y, s15 * y * z, 0.5f * s5 * (3.0f * z2 - 1.0f),
                     s15 * x * z, 0.5f * s15 * (x2 - y2) };
    float yv3[7] = { c33 * y * (3.0f * x2 - y2),
                     c32 * x * y * z,
                     c31 * y * (5.0f * z2 - 1.0f),
                     c30 * z * (5.0f * z2 - 3.0f),
                     c31 * x * (5.0f * z2 - 1.0f),
                     0.5f * c32 * z * (x2 - y2),
                     c33 * x * (x2 - 3.0f * y2) };

    int snd = __ldg(senders + e), rcv = __ldg(receivers + e);
    const float* sfeat = node_feats + (size_t)snd * 64;
    float* ob = out + (size_t)rcv * 1024;

    // ---- mix = h3 @ w4 (per irrep) + tensor product + scatter ----
    irrep_block<1>(ha, sw4,   0, sfeat, ob + 0,   yv0);  // 64x0e
    irrep_block<3>(ha, sw4,  64, sfeat, ob + 64,  yv1);  // 64x1o
    irrep_block<5>(ha, sw4, 128, sfeat, ob + 256, yv2);  // 64x2e
    irrep_block<7>(ha, sw4, 192, sfeat, ob + 576, yv3);  // 64x3o
}

extern "C" void kernel_launch(void* const* d_in, const int* in_sizes, int n_in,
                              void* d_out, int out_size)
{
    const float* vectors    = (const float*)d_in[0];
    const float* node_feats = (const float*)d_in[1];
    const float* radial     = (const float*)d_in[2];
    const float* w1         = (const float*)d_in[3];
    const float* w2         = (const float*)d_in[4];
    const float* w3         = (const float*)d_in[5];
    const float* w4         = (const float*)d_in[6];
    const int*   senders    = (const int*)d_in[7];
    const int*   receivers  = (const int*)d_in[8];
    float* out = (float*)d_out;

    int n_edges = in_sizes[7];

    cudaFuncSetAttribute(mpconv_kernel,
                         cudaFuncAttributeMaxDynamicSharedMemorySize,
                         SMEM_FLOATS * sizeof(float));

    cudaMemsetAsync(d_out, 0, (size_t)out_size * sizeof(float));

    int grid = (n_edges + TPB - 1) / TPB;
    mpconv_kernel<<<grid, TPB, SMEM_FLOATS * sizeof(float)>>>(
        vectors, node_feats, radial, w1, w2, w3, w4, senders, receivers,
        out, n_edges);
}

// round 2
// speedup vs baseline: 1.0551x; 1.0551x over previous
#include <cuda_runtime.h>

typedef unsigned long long u64;

#define TPB 128
#define SMEM_FLOATS 25088  // w1(512) + w2(4096) + w3(4096) + w4(16384)

// ---------- packed f32x2 helpers (PTX-only; ptxas won't auto-fuse) ----------
__device__ __forceinline__ u64 pack2(float a, float b) {
    u64 r; asm("mov.b64 %0, {%1, %2};" : "=l"(r) : "f"(a), "f"(b)); return r;
}
__device__ __forceinline__ u64 bcast2(float a) { return pack2(a, a); }
__device__ __forceinline__ u64 ffma2(u64 a, u64 b, u64 c) {
    u64 d; asm("fma.rn.f32x2 %0, %1, %2, %3;" : "=l"(d) : "l"(a), "l"(b), "l"(c)); return d;
}
__device__ __forceinline__ u64 fmul2(u64 a, u64 b) {
    u64 d; asm("mul.rn.f32x2 %0, %1, %2;" : "=l"(d) : "l"(a), "l"(b)); return d;
}
__device__ __forceinline__ void unpack2(float& lo, float& hi, u64 v) {
    asm("mov.b64 {%0, %1}, %2;" : "=f"(lo), "=f"(hi) : "l"(v));
}

// Vectorized global reduction (sm_90+): red.global.add.v4.f32
__device__ __forceinline__ void red4(float* p, float a, float b, float c, float d) {
    asm volatile("red.global.add.v4.f32 [%0], {%1, %2, %3, %4};"
                 :: "l"(p), "f"(a), "f"(b), "f"(c), "f"(d) : "memory");
}

__device__ __forceinline__ float silu(float x) {
    return __fdividef(x, 1.0f + __expf(-x));
}

// Dense layer NIN -> 64 for TWO edges sharing every weight load.
// Weights row-major [NIN][64] in shared. Output o = silu(acc*scale)*post.
template<int NIN>
__device__ __forceinline__ void dense2(const float* a0, const float* a1,
                                       const float* wsh, float scale,
                                       float post0, float post1,
                                       float* o0, float* o1)
{
    #pragma unroll 1
    for (int jc = 0; jc < 2; jc++) {
        u64 acc0[16], acc1[16];
        #pragma unroll
        for (int m = 0; m < 16; m++) { acc0[m] = 0ull; acc1[m] = 0ull; }
        #pragma unroll 2
        for (int i = 0; i < NIN; i++) {
            u64 h0 = bcast2(a0[i]);
            u64 h1 = bcast2(a1[i]);
            const ulonglong2* wr = (const ulonglong2*)(wsh + i * 64 + jc * 32);
            #pragma unroll
            for (int m = 0; m < 8; m++) {
                ulonglong2 w = wr[m];
                acc0[2*m]   = ffma2(h0, w.x, acc0[2*m]);
                acc0[2*m+1] = ffma2(h0, w.y, acc0[2*m+1]);
                acc1[2*m]   = ffma2(h1, w.x, acc1[2*m]);
                acc1[2*m+1] = ffma2(h1, w.y, acc1[2*m+1]);
            }
        }
        #pragma unroll
        for (int m = 0; m < 16; m++) {
            float x0, y0, x1, y1;
            unpack2(x0, y0, acc0[m]);
            unpack2(x1, y1, acc1[m]);
            o0[jc*32 + 2*m]     = silu(x0 * scale) * post0;
            o0[jc*32 + 2*m + 1] = silu(y0 * scale) * post0;
            o1[jc*32 + 2*m]     = silu(x1 * scale) * post1;
            o1[jc*32 + 2*m + 1] = silu(y1 * scale) * post1;
        }
    }
}

// One irrep of width W for TWO edges: mix = h3'@w4 (scales pre-folded into h3'),
// t = sender_feats * mix, message = t (x) Y, vector-reduced into out rows.
template<int W>
__device__ __forceinline__ void irrep2(const float* h0, const float* h1,
                                       const float* sw4, int col0,
                                       const float* __restrict__ sf0,
                                       const float* __restrict__ sf1,
                                       float* op0, float* op1,
                                       const float (&ya)[W], const float (&yb)[W])
{
    #pragma unroll 1
    for (int jc = 0; jc < 2; jc++) {
        u64 acc0[16], acc1[16];
        #pragma unroll
        for (int m = 0; m < 16; m++) { acc0[m] = 0ull; acc1[m] = 0ull; }
        #pragma unroll 2
        for (int i = 0; i < 64; i++) {
            u64 hv0 = bcast2(h0[i]);
            u64 hv1 = bcast2(h1[i]);
            const ulonglong2* wr = (const ulonglong2*)(sw4 + i * 256 + col0 + jc * 32);
            #pragma unroll
            for (int m = 0; m < 8; m++) {
                ulonglong2 w = wr[m];
                acc0[2*m]   = ffma2(hv0, w.x, acc0[2*m]);
                acc0[2*m+1] = ffma2(hv0, w.y, acc0[2*m+1]);
                acc1[2*m]   = ffma2(hv1, w.x, acc1[2*m]);
                acc1[2*m+1] = ffma2(hv1, w.y, acc1[2*m+1]);
            }
        }
        // tensor product + scatter for 8 groups of 4 channels
        #pragma unroll
        for (int g = 0; g < 8; g++) {
            const int c = jc * 32 + g * 4;
            // edge 0
            {
                u64 sa = __ldg((const u64*)(sf0 + c));
                u64 sb = __ldg((const u64*)(sf0 + c + 2));
                u64 pa = fmul2(acc0[2*g], sa);
                u64 pb = fmul2(acc0[2*g + 1], sb);
                float t[4];
                unpack2(t[0], t[1], pa);
                unpack2(t[2], t[3], pb);
                float vals[4 * W];
                #pragma unroll
                for (int q = 0; q < 4; q++)
                    #pragma unroll
                    for (int k = 0; k < W; k++)
                        vals[q * W + k] = t[q] * ya[k];
                float* p = op0 + c * W;
                #pragma unroll
                for (int m = 0; m < W; m++)
                    red4(p + 4*m, vals[4*m], vals[4*m+1], vals[4*m+2], vals[4*m+3]);
            }
            // edge 1
            {
                u64 sa = __ldg((const u64*)(sf1 + c));
                u64 sb = __ldg((const u64*)(sf1 + c + 2));
                u64 pa = fmul2(acc1[2*g], sa);
                u64 pb = fmul2(acc1[2*g + 1], sb);
                float t[4];
                unpack2(t[0], t[1], pa);
                unpack2(t[2], t[3], pb);
                float vals[4 * W];
                #pragma unroll
                for (int q = 0; q < 4; q++)
                    #pragma unroll
                    for (int k = 0; k < W; k++)
                        vals[q * W + k] = t[q] * yb[k];
                float* p = op1 + c * W;
                #pragma unroll
                for (int m = 0; m < W; m++)
                    red4(p + 4*m, vals[4*m], vals[4*m+1], vals[4*m+2], vals[4*m+3]);
            }
        }
    }
}

__device__ __forceinline__ void sph_all(float vx, float vy, float vz,
                                        float (&yv1)[3], float (&yv2)[5], float (&yv3)[7])
{
    float inv = 1.0f / (sqrtf(vx*vx + vy*vy + vz*vz) + 1e-12f);
    float x = vx * inv, y = vy * inv, z = vz * inv;

    const float s3  = 1.7320508075688772f;
    const float s5  = 2.23606797749979f;
    const float s15 = 3.872983346207417f;
    const float c33 = 2.091650066335189f;
    const float c32 = 10.246950765959598f;
    const float c31 = 1.6201851746019651f;
    const float c30 = 1.3228756555322954f;

    float z2 = z*z, x2 = x*x, y2 = y*y;
    yv1[0] = s3 * y; yv1[1] = s3 * z; yv1[2] = s3 * x;
    yv2[0] = s15 * x * y;
    yv2[1] = s15 * y * z;
    yv2[2] = 0.5f * s5 * (3.0f * z2 - 1.0f);
    yv2[3] = s15 * x * z;
    yv2[4] = 0.5f * s15 * (x2 - y2);
    yv3[0] = c33 * y * (3.0f * x2 - y2);
    yv3[1] = c32 * x * y * z;
    yv3[2] = c31 * y * (5.0f * z2 - 1.0f);
    yv3[3] = c30 * z * (5.0f * z2 - 3.0f);
    yv3[4] = c31 * x * (5.0f * z2 - 1.0f);
    yv3[5] = 0.5f * c32 * z * (x2 - y2);
    yv3[6] = c33 * x * (x2 - 3.0f * y2);
}

__global__ void __launch_bounds__(TPB, 2)
mpconv_kernel(const float* __restrict__ vectors,
              const float* __restrict__ node_feats,
              const float* __restrict__ radial,
              const float* __restrict__ w1, const float* __restrict__ w2,
              const float* __restrict__ w3, const float* __restrict__ w4,
              const int* __restrict__ senders, const int* __restrict__ receivers,
              float* __restrict__ out, int n_edges)
{
    extern __shared__ float smem[];
    float* sw1 = smem;           // 512
    float* sw2 = sw1 + 512;      // 4096
    float* sw3 = sw2 + 4096;     // 4096
    float* sw4 = sw3 + 4096;     // 16384

    {   // coalesced float4 weight staging
        float4* d1 = (float4*)sw1; const float4* s1 = (const float4*)w1;
        for (int i = threadIdx.x; i < 128; i += TPB) d1[i] = s1[i];
        float4* d2 = (float4*)sw2; const float4* s2 = (const float4*)w2;
        for (int i = threadIdx.x; i < 1024; i += TPB) d2[i] = s2[i];
        float4* d3 = (float4*)sw3; const float4* s3 = (const float4*)w3;
        for (int i = threadIdx.x; i < 1024; i += TPB) d3[i] = s3[i];
        float4* d4 = (float4*)sw4; const float4* s4 = (const float4*)w4;
        for (int i = threadIdx.x; i < 4096; i += TPB) d4[i] = s4[i];
    }
    __syncthreads();

    int e0 = blockIdx.x * (2 * TPB) + threadIdx.x;
    if (e0 >= n_edges) return;
    int e1 = e0 + TPB;
    bool valid1 = (e1 < n_edges);
    int ee1 = valid1 ? e1 : e0;

    // ---- radial inputs (coalesced float4) ----
    float r0[8], r1[8];
    {
        const float4* rp = (const float4*)(radial + (size_t)e0 * 8);
        float4 ra = __ldg(rp), rb = __ldg(rp + 1);
        r0[0]=ra.x; r0[1]=ra.y; r0[2]=ra.z; r0[3]=ra.w;
        r0[4]=rb.x; r0[5]=rb.y; r0[6]=rb.z; r0[7]=rb.w;
        const float4* rq = (const float4*)(radial + (size_t)ee1 * 8);
        float4 rc = __ldg(rq), rd = __ldg(rq + 1);
        r1[0]=rc.x; r1[1]=rc.y; r1[2]=rc.z; r1[3]=rc.w;
        r1[4]=rd.x; r1[5]=rd.y; r1[6]=rd.z; r1[7]=rd.w;
    }

    float ha0[64], ha1[64], hb0[64], hb1[64];
    // layer 1 (scale 1/sqrt(8)), layer 2, layer 3 (fold (1/8)*(1/4)=1/32 into h3; zero edge1 if invalid)
    dense2<8>(r0, r1, sw1, 0.35355339059327373f, 1.0f, 1.0f, ha0, ha1);
    dense2<64>(ha0, ha1, sw2, 0.125f, 1.0f, 1.0f, hb0, hb1);
    dense2<64>(hb0, hb1, sw3, 0.125f, 0.03125f, valid1 ? 0.03125f : 0.0f, ha0, ha1);

    // ---- geometry ----
    float ya1[3], ya2[5], ya3[7], yb1[3], yb2[5], yb3[7];
    {
        float vx = __ldg(vectors + 3*(size_t)e0 + 0);
        float vy = __ldg(vectors + 3*(size_t)e0 + 1);
        float vz = __ldg(vectors + 3*(size_t)e0 + 2);
        sph_all(vx, vy, vz, ya1, ya2, ya3);
        float ux = __ldg(vectors + 3*(size_t)ee1 + 0);
        float uy = __ldg(vectors + 3*(size_t)ee1 + 1);
        float uz = __ldg(vectors + 3*(size_t)ee1 + 2);
        sph_all(ux, uy, uz, yb1, yb2, yb3);
    }

    int snd0 = __ldg(senders + e0), rcv0 = __ldg(receivers + e0);
    int snd1 = __ldg(senders + ee1), rcv1 = __ldg(receivers + ee1);
    const float* sf0 = node_feats + (size_t)snd0 * 64;
    const float* sf1 = node_feats + (size_t)snd1 * 64;
    float* ob0 = out + (size_t)rcv0 * 1024;
    float* ob1 = out + (size_t)rcv1 * 1024;

    float y0a[1] = {1.0f}, y0b[1] = {1.0f};
    irrep2<1>(ha0, ha1, sw4,   0, sf0, sf1, ob0 + 0,   ob1 + 0,   y0a, y0b);
    irrep2<3>(ha0, ha1, sw4,  64, sf0, sf1, ob0 + 64,  ob1 + 64,  ya1, yb1);
    irrep2<5>(ha0, ha1, sw4, 128, sf0, sf1, ob0 + 256, ob1 + 256, ya2, yb2);
    irrep2<7>(ha0, ha1, sw4, 192, sf0, sf1, ob0 + 576, ob1 + 576, ya3, yb3);
}

extern "C" void kernel_launch(void* const* d_in, const int* in_sizes, int n_in,
                              void* d_out, int out_size)
{
    const float* vectors    = (const float*)d_in[0];
    const float* node_feats = (const float*)d_in[1];
    const float* radial     = (const float*)d_in[2];
    const float* w1         = (const float*)d_in[3];
    const float* w2         = (const float*)d_in[4];
    const float* w3         = (const float*)d_in[5];
    const float* w4         = (const float*)d_in[6];
    const int*   senders    = (const int*)d_in[7];
    const int*   receivers  = (const int*)d_in[8];
    float* out = (float*)d_out;

    int n_edges = in_sizes[7];

    cudaFuncSetAttribute(mpconv_kernel,
                         cudaFuncAttributeMaxDynamicSharedMemorySize,
                         SMEM_FLOATS * sizeof(float));

    cudaMemsetAsync(d_out, 0, (size_t)out_size * sizeof(float));

    int grid = (n_edges + 2 * TPB - 1) / (2 * TPB);
    mpconv_kernel<<<grid, TPB, SMEM_FLOATS * sizeof(float)>>>(
        vectors, node_feats, radial, w1, w2, w3, w4, senders, receivers,
        out, n_edges);
}

// round 3
// speedup vs baseline: 1.4308x; 1.3561x over previous
#include <cuda_runtime.h>

typedef unsigned long long u64;

#define N_EDGES_CAP 160000
__device__ float g_mix[(size_t)N_EDGES_CAP * 256];

#define TPB_A 192
#define SMEM_FLOATS 25088  // w1(512) + w2(4096) + w3(4096) + w4(16384)

// ---------- packed f32x2 helpers ----------
__device__ __forceinline__ u64 pack2(float a, float b) {
    u64 r; asm("mov.b64 %0, {%1, %2};" : "=l"(r) : "f"(a), "f"(b)); return r;
}
__device__ __forceinline__ u64 bcast2(float a) { return pack2(a, a); }
__device__ __forceinline__ u64 ffma2(u64 a, u64 b, u64 c) {
    u64 d; asm("fma.rn.f32x2 %0, %1, %2, %3;" : "=l"(d) : "l"(a), "l"(b), "l"(c)); return d;
}
__device__ __forceinline__ void unpack2(float& lo, float& hi, u64 v) {
    asm("mov.b64 {%0, %1}, %2;" : "=f"(lo), "=f"(hi) : "l"(v));
}

__device__ __forceinline__ void red4(float* p, float a, float b, float c, float d) {
    asm volatile("red.global.add.v4.f32 [%0], {%1, %2, %3, %4};"
                 :: "l"(p), "f"(a), "f"(b), "f"(c), "f"(d) : "memory");
}

__device__ __forceinline__ float silu(float x) {
    return __fdividef(x, 1.0f + __expf(-x));
}

// Dense NIN->64, single edge, fully unrolled (all activation indices static).
template<int NIN>
__device__ __forceinline__ void dense1(const float* __restrict__ a,
                                       const float* __restrict__ wsh,
                                       float scale, float post, float* __restrict__ o)
{
    #pragma unroll
    for (int jc = 0; jc < 2; jc++) {
        u64 acc[16];
        #pragma unroll
        for (int m = 0; m < 16; m++) acc[m] = 0ull;
        #pragma unroll
        for (int i = 0; i < NIN; i++) {
            u64 h = bcast2(a[i]);
            const ulonglong2* wr = (const ulonglong2*)(wsh + i * 64 + jc * 32);
            #pragma unroll
            for (int m = 0; m < 8; m++) {
                ulonglong2 w = wr[m];
                acc[2*m]   = ffma2(h, w.x, acc[2*m]);
                acc[2*m+1] = ffma2(h, w.y, acc[2*m+1]);
            }
        }
        #pragma unroll
        for (int m = 0; m < 16; m++) {
            float x, y; unpack2(x, y, acc[m]);
            o[jc*32 + 2*m]     = silu(x * scale) * post;
            o[jc*32 + 2*m + 1] = silu(y * scale) * post;
        }
    }
}

// ===================== Kernel A: radial MLP -> mix =====================
__global__ void __launch_bounds__(TPB_A, 2)
mlp_kernel(const float* __restrict__ radial,
           const float* __restrict__ w1, const float* __restrict__ w2,
           const float* __restrict__ w3, const float* __restrict__ w4,
           int n_edges)
{
    extern __shared__ float smem[];
    float* sw1 = smem;           // 512
    float* sw2 = sw1 + 512;      // 4096
    float* sw3 = sw2 + 4096;     // 4096
    float* sw4 = sw3 + 4096;     // 16384

    {
        float4* d1 = (float4*)sw1; const float4* s1 = (const float4*)w1;
        for (int i = threadIdx.x; i < 128; i += TPB_A) d1[i] = s1[i];
        float4* d2 = (float4*)sw2; const float4* s2 = (const float4*)w2;
        for (int i = threadIdx.x; i < 1024; i += TPB_A) d2[i] = s2[i];
        float4* d3 = (float4*)sw3; const float4* s3 = (const float4*)w3;
        for (int i = threadIdx.x; i < 1024; i += TPB_A) d3[i] = s3[i];
        float4* d4 = (float4*)sw4; const float4* s4 = (const float4*)w4;
        for (int i = threadIdx.x; i < 4096; i += TPB_A) d4[i] = s4[i];
    }
    __syncthreads();

    int e = blockIdx.x * TPB_A + threadIdx.x;
    if (e >= n_edges) return;

    float rr[8];
    {
        const float4* rp = (const float4*)(radial + (size_t)e * 8);
        float4 ra = __ldg(rp), rb = __ldg(rp + 1);
        rr[0]=ra.x; rr[1]=ra.y; rr[2]=ra.z; rr[3]=ra.w;
        rr[4]=rb.x; rr[5]=rb.y; rr[6]=rb.z; rr[7]=rb.w;
    }

    float ha[64], hb[64];
    dense1<8>(rr, sw1, 0.35355339059327373f, 1.0f, ha);     // layer 1
    dense1<64>(ha, sw2, 0.125f, 1.0f, hb);                  // layer 2
    // layer 3: fold (1/8 w4-norm)*(1/sqrt(16)) = 1/32 into h3
    dense1<64>(hb, sw3, 0.125f, 0.03125f, ha);

    // mix = h3 @ w4  (8 blocks of 32 output cols; runtime blk keeps code small,
    // all register-array indices remain compile-time)
    float* mrow = g_mix + (size_t)e * 256;
    #pragma unroll 1
    for (int blk = 0; blk < 8; blk++) {
        u64 acc[16];
        #pragma unroll
        for (int m = 0; m < 16; m++) acc[m] = 0ull;
        const float* wbase = sw4 + blk * 32;
        #pragma unroll
        for (int i = 0; i < 64; i++) {
            u64 h = bcast2(ha[i]);
            const ulonglong2* wr = (const ulonglong2*)(wbase + i * 256);
            #pragma unroll
            for (int m = 0; m < 8; m++) {
                ulonglong2 w = wr[m];
                acc[2*m]   = ffma2(h, w.x, acc[2*m]);
                acc[2*m+1] = ffma2(h, w.y, acc[2*m+1]);
            }
        }
        float4* mout = (float4*)(mrow + blk * 32);
        #pragma unroll
        for (int m = 0; m < 8; m++) {
            float4 v;
            unpack2(v.x, v.y, acc[2*m]);
            unpack2(v.z, v.w, acc[2*m+1]);
            mout[m] = v;
        }
    }
}

// ===================== Kernel B: tensor product + coalesced scatter =====================
// Position p in [0,1024): irrep regions
//   r0 [0,64)    W=1  t[p]
//   r1 [64,256)  W=3  tbase=64  ybase=0
//   r2 [256,576) W=5  tbase=128 ybase=3
//   r3 [576,1024)W=7  tbase=192 ybase=8
template<int W, int START, int TB, int YB, int MUL>
__device__ __forceinline__ float tpv(const float* tsh, const float* ysh, int p) {
    int pp = p - START;
    int c = (pp * MUL) >> 16;
    int k = pp - c * W;
    return tsh[TB + c] * ysh[YB + k];
}

#define TPB_B 256

__global__ void __launch_bounds__(TPB_B)
scatter_kernel(const float* __restrict__ vectors,
               const float* __restrict__ node_feats,
               const int* __restrict__ senders,
               const int* __restrict__ receivers,
               float* __restrict__ out, int n_edges)
{
    __shared__ float stage[TPB_B / 32][272];   // per-warp: t[256] + y[15]
    int warp = threadIdx.x >> 5, lane = threadIdx.x & 31;
    int e = blockIdx.x * (TPB_B / 32) + warp;
    if (e >= n_edges) return;

    float* tsh = stage[warp];
    float* ysh = tsh + 256;

    int snd = __ldg(senders + e), rcv = __ldg(receivers + e);

    // t[c] = node_feats[snd][c & 63] * mix[e][c], lane covers c = lane*8..+7
    {
        const float4* mp = (const float4*)(g_mix + (size_t)e * 256) + lane * 2;
        float4 m0 = __ldg(mp), m1 = __ldg(mp + 1);
        const float4* sp = (const float4*)(node_feats + (size_t)snd * 64) + (lane & 7) * 2;
        float4 s0 = __ldg(sp), s1 = __ldg(sp + 1);
        float4 t0 = make_float4(m0.x*s0.x, m0.y*s0.y, m0.z*s0.z, m0.w*s0.w);
        float4 t1 = make_float4(m1.x*s1.x, m1.y*s1.y, m1.z*s1.z, m1.w*s1.w);
        ((float4*)tsh)[lane*2]     = t0;
        ((float4*)tsh)[lane*2 + 1] = t1;
    }

    // spherical harmonics (all lanes compute; lane 0 stores 15 floats)
    {
        float vx = __ldg(vectors + 3*(size_t)e + 0);
        float vy = __ldg(vectors + 3*(size_t)e + 1);
        float vz = __ldg(vectors + 3*(size_t)e + 2);
        float inv = 1.0f / (sqrtf(vx*vx + vy*vy + vz*vz) + 1e-12f);
        float x = vx*inv, y = vy*inv, z = vz*inv;
        const float s3  = 1.7320508075688772f;
        const float s5  = 2.23606797749979f;
        const float s15 = 3.872983346207417f;
        const float c33 = 2.091650066335189f;
        const float c32 = 10.246950765959598f;
        const float c31 = 1.6201851746019651f;
        const float c30 = 1.3228756555322954f;
        float z2 = z*z, x2 = x*x, y2 = y*y;
        if (lane == 0) {
            ysh[0]  = s3 * y;  ysh[1] = s3 * z;  ysh[2] = s3 * x;
            ysh[3]  = s15 * x * y;
            ysh[4]  = s15 * y * z;
            ysh[5]  = 0.5f * s5 * (3.0f * z2 - 1.0f);
            ysh[6]  = s15 * x * z;
            ysh[7]  = 0.5f * s15 * (x2 - y2);
            ysh[8]  = c33 * y * (3.0f * x2 - y2);
            ysh[9]  = c32 * x * y * z;
            ysh[10] = c31 * y * (5.0f * z2 - 1.0f);
            ysh[11] = c30 * z * (5.0f * z2 - 3.0f);
            ysh[12] = c31 * x * (5.0f * z2 - 1.0f);
            ysh[13] = 0.5f * c32 * z * (x2 - y2);
            ysh[14] = c33 * x * (x2 - 3.0f * y2);
        }
    }
    __syncwarp();

    float* ob = out + (size_t)rcv * 1024;

    #pragma unroll
    for (int j = 0; j < 8; j++) {
        int p0 = j * 128 + lane * 4;
        float v0, v1, v2, v3;
        if (j == 0) {
            if (lane < 16) {  // r0: scalars, y=1
                v0 = tsh[p0]; v1 = tsh[p0+1]; v2 = tsh[p0+2]; v3 = tsh[p0+3];
            } else {          // r1
                v0 = tpv<3,64,64,0,21846>(tsh, ysh, p0);
                v1 = tpv<3,64,64,0,21846>(tsh, ysh, p0+1);
                v2 = tpv<3,64,64,0,21846>(tsh, ysh, p0+2);
                v3 = tpv<3,64,64,0,21846>(tsh, ysh, p0+3);
            }
        } else if (j == 1) {  // r1
            v0 = tpv<3,64,64,0,21846>(tsh, ysh, p0);
            v1 = tpv<3,64,64,0,21846>(tsh, ysh, p0+1);
            v2 = tpv<3,64,64,0,21846>(tsh, ysh, p0+2);
            v3 = tpv<3,64,64,0,21846>(tsh, ysh, p0+3);
        } else if (j == 2 || j == 3) {  // r2
            v0 = tpv<5,256,128,3,13108>(tsh, ysh, p0);
            v1 = tpv<5,256,128,3,13108>(tsh, ysh, p0+1);
            v2 = tpv<5,256,128,3,13108>(tsh, ysh, p0+2);
            v3 = tpv<5,256,128,3,13108>(tsh, ysh, p0+3);
        } else if (j == 4) {
            if (lane < 16) {  // r2 tail
                v0 = tpv<5,256,128,3,13108>(tsh, ysh, p0);
                v1 = tpv<5,256,128,3,13108>(tsh, ysh, p0+1);
                v2 = tpv<5,256,128,3,13108>(tsh, ysh, p0+2);
                v3 = tpv<5,256,128,3,13108>(tsh, ysh, p0+3);
            } else {          // r3 head
                v0 = tpv<7,576,192,8,9363>(tsh, ysh, p0);
                v1 = tpv<7,576,192,8,9363>(tsh, ysh, p0+1);
                v2 = tpv<7,576,192,8,9363>(tsh, ysh, p0+2);
                v3 = tpv<7,576,192,8,9363>(tsh, ysh, p0+3);
            }
        } else {              // r3
            v0 = tpv<7,576,192,8,9363>(tsh, ysh, p0);
            v1 = tpv<7,576,192,8,9363>(tsh, ysh, p0+1);
            v2 = tpv<7,576,192,8,9363>(tsh, ysh, p0+2);
            v3 = tpv<7,576,192,8,9363>(tsh, ysh, p0+3);
        }
        red4(ob + p0, v0, v1, v2, v3);
    }
}

extern "C" void kernel_launch(void* const* d_in, const int* in_sizes, int n_in,
                              void* d_out, int out_size)
{
    const float* vectors    = (const float*)d_in[0];
    const float* node_feats = (const float*)d_in[1];
    const float* radial     = (const float*)d_in[2];
    const float* w1         = (const float*)d_in[3];
    const float* w2         = (const float*)d_in[4];
    const float* w3         = (const float*)d_in[5];
    const float* w4         = (const float*)d_in[6];
    const int*   senders    = (const int*)d_in[7];
    const int*   receivers  = (const int*)d_in[8];
    float* out = (float*)d_out;

    int n_edges = in_sizes[7];

    cudaFuncSetAttribute(mlp_kernel,
                         cudaFuncAttributeMaxDynamicSharedMemorySize,
                         SMEM_FLOATS * sizeof(float));

    cudaMemsetAsync(d_out, 0, (size_t)out_size * sizeof(float));

    int grid_a = (n_edges + TPB_A - 1) / TPB_A;
    mlp_kernel<<<grid_a, TPB_A, SMEM_FLOATS * sizeof(float)>>>(
        radial, w1, w2, w3, w4, n_edges);

    int edges_per_blk = TPB_B / 32;
    int grid_b = (n_edges + edges_per_blk - 1) / edges_per_blk;
    scatter_kernel<<<grid_b, TPB_B>>>(vectors, node_feats, senders, receivers,
                                      out, n_edges);
}